// round 10
// baseline (speedup 1.0000x reference)
#include <cuda_runtime.h>
#include <cstdint>

#define NN 2000000
#define DD 128
#define BB 1024
#define STEPS 3
#define CHUNKS 16                // chunks per graph
#define NPART (BB * CHUNKS)      // 16384 partial slots
#define TILE 16                  // nodes per pipeline stage
#define NSTAGE 4

// ---------------- device scratch (no allocs allowed) ----------------
__device__ int   g_is64;
__device__ int   g_off[BB + 1];
__device__ float g_h[BB * DD];
__device__ float g_c[BB * DD];
__device__ float g_r[BB * DD];
__device__ float g_Wt[64 * 512 * 4];       // [k4][gate_col][4k] transposed-tiled
__device__ float g_bias[4 * DD];
__device__ float g_pm[NPART];              // per-chunk running max
__device__ float g_ps[NPART];              // per-chunk exp-sum
__device__ float g_pr[NPART * DD];         // per-chunk pooled partial (8 MB)

__device__ __forceinline__ float sigf(float v) { return 1.f / (1.f + __expf(-v)); }

__device__ __forceinline__ void cp_async16(unsigned int dst, const void* src) {
    asm volatile("cp.async.cg.shared.global [%0], [%1], 16;" :: "r"(dst), "l"(src));
}

__device__ __forceinline__ float warp_sum(float d) {
    d += __shfl_xor_sync(0xffffffffu, d, 16);
    d += __shfl_xor_sync(0xffffffffu, d, 8);
    d += __shfl_xor_sync(0xffffffffu, d, 4);
    d += __shfl_xor_sync(0xffffffffu, d, 2);
    d += __shfl_xor_sync(0xffffffffu, d, 1);
    return d;
}

// ---------------- setup: weight fold (transposed-tiled) + bias + step0 LSTM ---
// gates = [h_prev, r_prev] @ Weff^T + (b_ih + b_hh)
// Weff[gc, 0:128] = W_ih[gc, 0:128] + W_hh[gc] ; Weff[gc, 128:256] = W_ih[gc, 128:256]
// Stored transposed-tiled: g_Wt[(k>>2)*2048 + gc*4 + (k&3)] = Weff[gc][k]
// Step 0: q*=0, h=0, c=0 => gates = bias => h0,c0 closed form.
// int64 detect: sorted values < 2^31 => odd int32 words all zero.
__global__ void setup_kernel(const float* __restrict__ W_ih, const float* __restrict__ W_hh,
                             const float* __restrict__ b_ih, const float* __restrict__ b_hh,
                             const int* __restrict__ bi32) {
    int id = blockIdx.x * blockDim.x + threadIdx.x;  // 131072 threads == BB*128
    int gc = id >> 8, k = id & 255;
    float w = W_ih[gc * 256 + k];
    if (k < 128) w += W_hh[gc * 128 + k];
    g_Wt[(k >> 2) * 2048 + gc * 4 + (k & 3)] = w;
    if (id < 4 * DD) g_bias[id] = b_ih[id] + b_hh[id];

    // step-0 LSTM state (one thread per (graph, channel))
    int c = id & 127;
    float gi = b_ih[c]       + b_hh[c];
    float gG = b_ih[c + 256] + b_hh[c + 256];
    float go = b_ih[c + 384] + b_hh[c + 384];
    float cn = sigf(gi) * tanhf(gG);        // sig(f)*c0 term is 0
    float hn = sigf(go) * tanhf(cn);
    g_c[id] = cn;
    g_h[id] = hn;

    if (id == 0)
        g_is64 = (bi32[NN - 1] == 0 && bi32[(NN / 2) | 1] == 0 &&
                  bi32[(NN / 4) | 1] == 0) ? 1 : 0;
}

__device__ __forceinline__ int load_bi(const void* bi, int i, int is64) {
    if (is64) return (int)((const long long*)bi)[i];
    return ((const int*)bi)[i];
}

// ---------------- graph start offsets (batch_index sorted), 8 elems/thread ----
__global__ void offsets_kernel(const void* __restrict__ bi) {
    int t = blockIdx.x * blockDim.x + threadIdx.x;
    if (t >= NN / 8) return;
    int i0 = t * 8;
    int is64 = g_is64;
    int v[8];
    if (is64) {
        const longlong2* p = (const longlong2*)bi + t * 4;
        longlong2 a = p[0], b = p[1], c = p[2], d = p[3];
        v[0] = (int)a.x; v[1] = (int)a.y; v[2] = (int)b.x; v[3] = (int)b.y;
        v[4] = (int)c.x; v[5] = (int)c.y; v[6] = (int)d.x; v[7] = (int)d.y;
    } else {
        const int4* p = (const int4*)bi + t * 2;
        int4 a = p[0], b = p[1];
        v[0] = a.x; v[1] = a.y; v[2] = a.z; v[3] = a.w;
        v[4] = b.x; v[5] = b.y; v[6] = b.z; v[7] = b.w;
    }
    int prev = (i0 == 0) ? -1 : load_bi(bi, i0 - 1, is64);
    #pragma unroll
    for (int j = 0; j < 8; ++j) {
        for (int g = prev + 1; g <= v[j]; ++g) g_off[g] = i0 + j;
        prev = v[j];
    }
    if (i0 + 8 == NN)
        for (int g = prev + 1; g <= BB; ++g) g_off[g] = NN;
}

// ---------------- chunked online-softmax attention pooling (partials) --------
// Block b handles chunk (b & 15) of graph (b >> 4). 4-stage cp.async pipeline,
// 3 tiles in flight; 6 blocks/SM.
__global__ __launch_bounds__(256, 6) void attn_kernel(const float* __restrict__ x) {
    __shared__ float4 s_tile[NSTAGE][TILE * 32];   // 4 x 8KB
    __shared__ float  s_q[128];
    __shared__ float  s_r[8][128];
    __shared__ float  s_m[8];
    __shared__ float  s_s[8];

    int b = blockIdx.x;
    int g = b >> 4, cidx = b & 15;
    int tid = threadIdx.x;
    int lane = tid & 31, wid = tid >> 5;

    if (tid < 128) s_q[tid] = g_h[g * DD + tid];

    int gs = g_off[g], ge = g_off[g + 1], len = ge - gs;
    int start = gs + (len * cidx) / CHUNKS;
    int end   = gs + (len * (cidx + 1)) / CHUNKS;
    int nt = (end > start) ? (end - start + TILE - 1) / TILE : 0;

    unsigned int s_base = (unsigned int)__cvta_generic_to_shared(s_tile);
    const float4* x4 = (const float4*)x;

    // issue tile t into buffer t % NSTAGE (clamped tail); always commit a group
    auto issue_tile = [&](int t) {
        if (t < nt) {
            int base = start + t * TILE;
            unsigned int dst0 = s_base + (unsigned int)((t % NSTAGE) * (TILE * 32) << 4);
            #pragma unroll
            for (int k = 0; k < 2; ++k) {
                int c = tid + 256 * k;            // 0..511 (16B chunk index)
                int node = base + (c >> 5);
                if (node >= end) node = end - 1;  // tail clamp: L2-hit duplicate
                cp_async16(dst0 + ((unsigned int)c << 4),
                           x4 + (size_t)node * 32 + (c & 31));
            }
        }
        asm volatile("cp.async.commit_group;" ::: "memory");
    };

    issue_tile(0);
    issue_tile(1);
    issue_tile(2);

    float m = -3.4e38f;
    float s = 0.f;
    float4 racc = make_float4(0.f, 0.f, 0.f, 0.f);
    float4 q4;

    __syncthreads();              // s_q visible (also covers nt==0 path)
    q4 = ((const float4*)s_q)[lane];

    for (int t = 0; t < nt; ++t) {
        asm volatile("cp.async.wait_group 2;" ::: "memory");  // tile t ready
        __syncthreads();          // all warps done with buf (t-1)%4 == (t+3)%4
        issue_tile(t + 3);        // refill newest stage

        const float4* tile = s_tile[t % NSTAGE];
        int nbase = start + t * TILE;
        float4 xv[2];
        float e[2];
        #pragma unroll
        for (int j = 0; j < 2; ++j) {
            int nl = wid * 2 + j;                 // 0..15
            xv[j] = tile[(nl << 5) + lane];
            float d = xv[j].x * q4.x + xv[j].y * q4.y +
                      xv[j].z * q4.z + xv[j].w * q4.w;
            d = warp_sum(d);
            e[j] = (nbase + nl < end) ? d : -3.4e38f;  // padded -> p = 0
        }
        float em = fmaxf(e[0], e[1]);
        if (em > m) {             // rare, warp-uniform
            float sc = __expf(m - em);
            s *= sc;
            racc.x *= sc; racc.y *= sc; racc.z *= sc; racc.w *= sc;
            m = em;
        }
        #pragma unroll
        for (int j = 0; j < 2; ++j) {
            float p = __expf(e[j] - m);
            s += p;
            racc.x += p * xv[j].x; racc.y += p * xv[j].y;
            racc.z += p * xv[j].z; racc.w += p * xv[j].w;
        }
    }

    if (lane == 0) { s_m[wid] = m; s_s[wid] = s; }
    ((float4*)s_r[wid])[lane] = racc;
    __syncthreads();

    // combine 8 per-warp partials -> per-chunk partial
    if (tid < 128) {
        float M = -3.4e38f;
        #pragma unroll
        for (int w = 0; w < 8; ++w)
            if (s_s[w] > 0.f && s_m[w] > M) M = s_m[w];
        float S = 0.f, rs = 0.f;
        #pragma unroll
        for (int w = 0; w < 8; ++w) {
            if (s_s[w] > 0.f) {
                float sc = __expf(s_m[w] - M);
                S  += s_s[w] * sc;
                rs += s_r[w][tid] * sc;
            }
        }
        g_pr[b * DD + tid] = rs;
        if (tid == 0) { g_pm[b] = M; g_ps[b] = S; }
    }
}

// ---------------- combine chunk partials -> g_r ----------------
__global__ __launch_bounds__(128) void combine_r_kernel() {
    int g = blockIdx.x, tid = threadIdx.x;
    float M = -3.4e38f;
    #pragma unroll
    for (int w = 0; w < CHUNKS; ++w) {
        float sw = g_ps[g * CHUNKS + w], mw = g_pm[g * CHUNKS + w];
        if (sw > 0.f && mw > M) M = mw;
    }
    float S = 0.f, rs = 0.f;
    #pragma unroll
    for (int w = 0; w < CHUNKS; ++w) {
        float sw = g_ps[g * CHUNKS + w];
        if (sw > 0.f) {
            float sc = __expf(g_pm[g * CHUNKS + w] - M);
            S  += sw * sc;
            rs += g_pr[(g * CHUNKS + w) * DD + tid] * sc;
        }
    }
    g_r[g * DD + tid] = (S > 0.f) ? rs / (S + 1e-16f) : 0.f;
}

// ---------------- LSTM GEMM + activation (coalesced transposed weights) ------
// Grid (128, 4): bx = graph octet, by = channel quarter (32 channels x 4 gates).
// Thread: (channel = by*32 + tid&31, gate = (tid>>5)&3, graph-quad = tid>>7).
// 1024 FFMA/thread; FFMA-issue bound (~7.6us floor across 512 blocks).
__global__ __launch_bounds__(256) void gemm_act_kernel() {
    __shared__ float s_in[8][256];        // [h | r] for 8 graphs (8 KB)
    __shared__ float s_gate[8][32][4];    // [graph][channel][gate] (4 KB)

    int g0 = blockIdx.x * 8;
    int by = blockIdx.y;
    int tid = threadIdx.x;

    for (int it = tid; it < 8 * 256; it += 256) {
        int g = it >> 8, k = it & 255;
        s_in[g][k] = (k < 128) ? g_h[(g0 + g) * DD + k]
                               : g_r[(g0 + g) * DD + (k - 128)];
    }
    __syncthreads();

    int c2 = tid & 31;            // channel-in-quarter
    int gt = (tid >> 5) & 3;      // gate index (i,f,g,o)
    int gp = tid >> 7;            // graph-quad (0..1)
    int col = gt * 128 + by * 32 + c2;

    float a0 = 0.f, a1 = 0.f, a2 = 0.f, a3 = 0.f;
    const float4* wt = (const float4*)g_Wt + col;     // + k4*512
    const float4* i0 = (const float4*)s_in[gp * 4 + 0];
    const float4* i1 = (const float4*)s_in[gp * 4 + 1];
    const float4* i2 = (const float4*)s_in[gp * 4 + 2];
    const float4* i3 = (const float4*)s_in[gp * 4 + 3];
    #pragma unroll 8
    for (int k4 = 0; k4 < 64; ++k4) {
        float4 w = wt[k4 * 512];
        float4 v0 = i0[k4], v1 = i1[k4], v2 = i2[k4], v3 = i3[k4];
        a0 += w.x * v0.x + w.y * v0.y + w.z * v0.z + w.w * v0.w;
        a1 += w.x * v1.x + w.y * v1.y + w.z * v1.z + w.w * v1.w;
        a2 += w.x * v2.x + w.y * v2.y + w.z * v2.z + w.w * v2.w;
        a3 += w.x * v3.x + w.y * v3.y + w.z * v3.z + w.w * v3.w;
    }
    float bia = g_bias[col];
    s_gate[gp * 4 + 0][c2][gt] = a0 + bia;
    s_gate[gp * 4 + 1][c2][gt] = a1 + bia;
    s_gate[gp * 4 + 2][c2][gt] = a2 + bia;
    s_gate[gp * 4 + 3][c2][gt] = a3 + bia;
    __syncthreads();

    // activation: thread -> (graph = tid>>5, channel = tid&31)
    int g = tid >> 5, ch = tid & 31;
    float gi = s_gate[g][ch][0];
    float gf = s_gate[g][ch][1];
    float gG = s_gate[g][ch][2];
    float go = s_gate[g][ch][3];
    int idx = (g0 + g) * DD + by * 32 + ch;
    float cn = sigf(gf) * g_c[idx] + sigf(gi) * tanhf(gG);
    float hn = sigf(go) * tanhf(cn);
    g_c[idx] = cn;
    g_h[idx] = hn;
}

// ---------------- final combine: r from partials, write [q, r] ---------------
__global__ __launch_bounds__(128) void combine_out_kernel(float* __restrict__ out) {
    int g = blockIdx.x, tid = threadIdx.x;
    float M = -3.4e38f;
    #pragma unroll
    for (int w = 0; w < CHUNKS; ++w) {
        float sw = g_ps[g * CHUNKS + w], mw = g_pm[g * CHUNKS + w];
        if (sw > 0.f && mw > M) M = mw;
    }
    float S = 0.f, rs = 0.f;
    #pragma unroll
    for (int w = 0; w < CHUNKS; ++w) {
        float sw = g_ps[g * CHUNKS + w];
        if (sw > 0.f) {
            float sc = __expf(g_pm[g * CHUNKS + w] - M);
            S  += sw * sc;
            rs += g_pr[(g * CHUNKS + w) * DD + tid] * sc;
        }
    }
    float rf = (S > 0.f) ? rs / (S + 1e-16f) : 0.f;
    out[g * 2 * DD + tid]      = g_h[g * DD + tid];  // q
    out[g * 2 * DD + DD + tid] = rf;                 // r
}

// ---------------- launch (10 kernels) ----------------
extern "C" void kernel_launch(void* const* d_in, const int* in_sizes, int n_in,
                              void* d_out, int out_size) {
    const float* x    = (const float*)d_in[0];
    const void*  bi   = d_in[1];
    const float* W_ih = (const float*)d_in[2];
    const float* W_hh = (const float*)d_in[3];
    const float* b_ih = (const float*)d_in[4];
    const float* b_hh = (const float*)d_in[5];
    float* out = (float*)d_out;

    setup_kernel<<<512, 256>>>(W_ih, W_hh, b_ih, b_hh, (const int*)bi);
    offsets_kernel<<<(NN / 8 + 255) / 256, 256>>>(bi);
    attn_kernel<<<NPART, 256>>>(x);
    combine_r_kernel<<<BB, 128>>>();
    gemm_act_kernel<<<dim3(BB / 8, 4), 256>>>();
    attn_kernel<<<NPART, 256>>>(x);
    combine_r_kernel<<<BB, 128>>>();
    gemm_act_kernel<<<dim3(BB / 8, 4), 256>>>();
    attn_kernel<<<NPART, 256>>>(x);
    combine_out_kernel<<<BB, 128>>>(out);
}

// round 12
// speedup vs baseline: 1.0162x; 1.0162x over previous
#include <cuda_runtime.h>
#include <cstdint>

#define NN 2000000
#define DD 128
#define BB 1024
#define STEPS 3
#define CHUNKS 8                 // chunks per graph
#define NPART (BB * CHUNKS)      // 8192 partial slots
#define TILE 16                  // nodes per pipeline stage
#define NSTAGE 4

// ---------------- device scratch (no allocs allowed) ----------------
__device__ int   g_is64;
__device__ int   g_off[BB + 1];
__device__ float g_h[BB * DD];
__device__ float g_c[BB * DD];
__device__ float g_Wt[64 * 512 * 4];       // [k4][gate_col][4k] transposed-tiled
__device__ float g_bias[4 * DD];
__device__ float g_pm[NPART];              // per-chunk running max
__device__ float g_ps[NPART];              // per-chunk exp-sum
__device__ float g_pr[NPART * DD];         // per-chunk pooled partial (4 MB)

__device__ __forceinline__ float sigf(float v) { return 1.f / (1.f + __expf(-v)); }

__device__ __forceinline__ void cp_async16(unsigned int dst, const void* src) {
    asm volatile("cp.async.cg.shared.global [%0], [%1], 16;" :: "r"(dst), "l"(src));
}

__device__ __forceinline__ float warp_sum(float d) {
    d += __shfl_xor_sync(0xffffffffu, d, 16);
    d += __shfl_xor_sync(0xffffffffu, d, 8);
    d += __shfl_xor_sync(0xffffffffu, d, 4);
    d += __shfl_xor_sync(0xffffffffu, d, 2);
    d += __shfl_xor_sync(0xffffffffu, d, 1);
    return d;
}

// ---------------- setup: weight fold (transposed-tiled) + bias + step0 LSTM ---
// gates = [h_prev, r_prev] @ Weff^T + (b_ih + b_hh)
// Weff[gc, 0:128] = W_ih[gc, 0:128] + W_hh[gc] ; Weff[gc, 128:256] = W_ih[gc, 128:256]
// Stored transposed-tiled: g_Wt[(k>>2)*2048 + gc*4 + (k&3)] = Weff[gc][k]
// Step 0: q*=0, h=0, c=0 => gates = bias => h0,c0 closed form.
// int64 detect: sorted values < 2^31 => odd int32 words all zero.
__global__ void setup_kernel(const float* __restrict__ W_ih, const float* __restrict__ W_hh,
                             const float* __restrict__ b_ih, const float* __restrict__ b_hh,
                             const int* __restrict__ bi32) {
    int id = blockIdx.x * blockDim.x + threadIdx.x;  // 131072 threads == BB*128
    int gc = id >> 8, k = id & 255;
    float w = W_ih[gc * 256 + k];
    if (k < 128) w += W_hh[gc * 128 + k];
    g_Wt[(k >> 2) * 2048 + gc * 4 + (k & 3)] = w;
    if (id < 4 * DD) g_bias[id] = b_ih[id] + b_hh[id];

    // step-0 LSTM state (one thread per (graph, channel))
    int c = id & 127;
    float gi = b_ih[c]       + b_hh[c];
    float gG = b_ih[c + 256] + b_hh[c + 256];
    float go = b_ih[c + 384] + b_hh[c + 384];
    float cn = sigf(gi) * tanhf(gG);        // sig(f)*c0 term is 0
    float hn = sigf(go) * tanhf(cn);
    g_c[id] = cn;
    g_h[id] = hn;

    if (id == 0)
        g_is64 = (bi32[NN - 1] == 0 && bi32[(NN / 2) | 1] == 0 &&
                  bi32[(NN / 4) | 1] == 0) ? 1 : 0;
}

__device__ __forceinline__ int load_bi(const void* bi, int i, int is64) {
    if (is64) return (int)((const long long*)bi)[i];
    return ((const int*)bi)[i];
}

// ---------------- graph start offsets (batch_index sorted), 8 elems/thread ----
__global__ void offsets_kernel(const void* __restrict__ bi) {
    int t = blockIdx.x * blockDim.x + threadIdx.x;
    if (t >= NN / 8) return;
    int i0 = t * 8;
    int is64 = g_is64;
    int v[8];
    if (is64) {
        const longlong2* p = (const longlong2*)bi + t * 4;
        longlong2 a = p[0], b = p[1], c = p[2], d = p[3];
        v[0] = (int)a.x; v[1] = (int)a.y; v[2] = (int)b.x; v[3] = (int)b.y;
        v[4] = (int)c.x; v[5] = (int)c.y; v[6] = (int)d.x; v[7] = (int)d.y;
    } else {
        const int4* p = (const int4*)bi + t * 2;
        int4 a = p[0], b = p[1];
        v[0] = a.x; v[1] = a.y; v[2] = a.z; v[3] = a.w;
        v[4] = b.x; v[5] = b.y; v[6] = b.z; v[7] = b.w;
    }
    int prev = (i0 == 0) ? -1 : load_bi(bi, i0 - 1, is64);
    #pragma unroll
    for (int j = 0; j < 8; ++j) {
        for (int g = prev + 1; g <= v[j]; ++g) g_off[g] = i0 + j;
        prev = v[j];
    }
    if (i0 + 8 == NN)
        for (int g = prev + 1; g <= BB; ++g) g_off[g] = NN;
}

// ---------------- chunked online-softmax attention pooling (partials) --------
// Block b handles chunk (b & 7) of graph (b >> 3). 4-stage cp.async pipeline,
// 3 tiles in flight; 6 blocks/SM.
__global__ __launch_bounds__(256, 6) void attn_kernel(const float* __restrict__ x) {
    __shared__ float4 s_tile[NSTAGE][TILE * 32];   // 4 x 8KB
    __shared__ float  s_q[128];
    __shared__ float  s_r[8][128];
    __shared__ float  s_m[8];
    __shared__ float  s_s[8];

    int b = blockIdx.x;
    int g = b >> 3, cidx = b & 7;
    int tid = threadIdx.x;
    int lane = tid & 31, wid = tid >> 5;

    if (tid < 128) s_q[tid] = g_h[g * DD + tid];

    int gs = g_off[g], ge = g_off[g + 1], len = ge - gs;
    int start = gs + (len * cidx) / CHUNKS;
    int end   = gs + (len * (cidx + 1)) / CHUNKS;
    int nt = (end > start) ? (end - start + TILE - 1) / TILE : 0;

    unsigned int s_base = (unsigned int)__cvta_generic_to_shared(s_tile);
    const float4* x4 = (const float4*)x;

    // issue tile t into buffer t % NSTAGE (clamped tail); always commit a group
    auto issue_tile = [&](int t) {
        if (t < nt) {
            int base = start + t * TILE;
            unsigned int dst0 = s_base + (unsigned int)((t % NSTAGE) * (TILE * 32) << 4);
            #pragma unroll
            for (int k = 0; k < 2; ++k) {
                int c = tid + 256 * k;            // 0..511 (16B chunk index)
                int node = base + (c >> 5);
                if (node >= end) node = end - 1;  // tail clamp: L2-hit duplicate
                cp_async16(dst0 + ((unsigned int)c << 4),
                           x4 + (size_t)node * 32 + (c & 31));
            }
        }
        asm volatile("cp.async.commit_group;" ::: "memory");
    };

    issue_tile(0);
    issue_tile(1);
    issue_tile(2);

    float m = -3.4e38f;
    float s = 0.f;
    float4 racc = make_float4(0.f, 0.f, 0.f, 0.f);
    float4 q4;

    __syncthreads();              // s_q visible (also covers nt==0 path)
    q4 = ((const float4*)s_q)[lane];

    for (int t = 0; t < nt; ++t) {
        asm volatile("cp.async.wait_group 2;" ::: "memory");  // tile t ready
        __syncthreads();          // all warps done with buf (t-1)%4 == (t+3)%4
        issue_tile(t + 3);        // refill newest stage

        const float4* tile = s_tile[t % NSTAGE];
        int nbase = start + t * TILE;
        float4 xv[2];
        float e[2];
        #pragma unroll
        for (int j = 0; j < 2; ++j) {
            int nl = wid * 2 + j;                 // 0..15
            xv[j] = tile[(nl << 5) + lane];
            float d = xv[j].x * q4.x + xv[j].y * q4.y +
                      xv[j].z * q4.z + xv[j].w * q4.w;
            d = warp_sum(d);
            e[j] = (nbase + nl < end) ? d : -3.4e38f;  // padded -> p = 0
        }
        float em = fmaxf(e[0], e[1]);
        if (em > m) {             // rare, warp-uniform
            float sc = __expf(m - em);
            s *= sc;
            racc.x *= sc; racc.y *= sc; racc.z *= sc; racc.w *= sc;
            m = em;
        }
        #pragma unroll
        for (int j = 0; j < 2; ++j) {
            float p = __expf(e[j] - m);
            s += p;
            racc.x += p * xv[j].x; racc.y += p * xv[j].y;
            racc.z += p * xv[j].z; racc.w += p * xv[j].w;
        }
    }

    if (lane == 0) { s_m[wid] = m; s_s[wid] = s; }
    ((float4*)s_r[wid])[lane] = racc;
    __syncthreads();

    // combine 8 per-warp partials -> per-chunk partial
    if (tid < 128) {
        float M = -3.4e38f;
        #pragma unroll
        for (int w = 0; w < 8; ++w)
            if (s_s[w] > 0.f && s_m[w] > M) M = s_m[w];
        float S = 0.f, rs = 0.f;
        #pragma unroll
        for (int w = 0; w < 8; ++w) {
            if (s_s[w] > 0.f) {
                float sc = __expf(s_m[w] - M);
                S  += s_s[w] * sc;
                rs += s_r[w][tid] * sc;
            }
        }
        g_pr[b * DD + tid] = rs;
        if (tid == 0) { g_pm[b] = M; g_ps[b] = S; }
    }
}

// ---------------- fused: combine partials -> r (in smem), GEMM, activation ---
// Grid (128, 4): bx = graph octet, by = channel quarter (32 channels x 4 gates).
// Each block combines r for its 8 graphs directly from g_pr (L2-resident,
// 32 KB/block), then computes its quarter of the gates and updates h, c.
__global__ __launch_bounds__(256) void gemm_act_kernel() {
    __shared__ float s_in[8][256];        // [h | r] for 8 graphs (8 KB)
    __shared__ float s_gate[8][32][4];    // [graph][channel][gate] (4 KB)
    __shared__ float s_scale[8][CHUNKS];
    __shared__ float s_S[8];

    int g0 = blockIdx.x * 8;
    int by = blockIdx.y;
    int tid = threadIdx.x;

    // per-graph softmax-combine scales (8 threads)
    if (tid < 8) {
        int g = g0 + tid;
        float M = -3.4e38f;
        #pragma unroll
        for (int w = 0; w < CHUNKS; ++w) {
            float sw = g_ps[g * CHUNKS + w], mw = g_pm[g * CHUNKS + w];
            if (sw > 0.f && mw > M) M = mw;
        }
        float S = 0.f;
        #pragma unroll
        for (int w = 0; w < CHUNKS; ++w) {
            float sw = g_ps[g * CHUNKS + w];
            float sc = (sw > 0.f) ? __expf(g_pm[g * CHUNKS + w] - M) : 0.f;
            s_scale[tid][w] = sc;
            S += sw * sc;
        }
        s_S[tid] = S;
    }
    // h into s_in[:, 0:128]
    for (int it = tid; it < 8 * 128; it += 256) {
        int g = it >> 7, c = it & 127;
        s_in[g][c] = g_h[(g0 + g) * DD + c];
    }
    __syncthreads();
    // r into s_in[:, 128:256] (combine partials; g_pr reads are L2 hits)
    for (int it = tid; it < 8 * 128; it += 256) {
        int g = it >> 7, c = it & 127;
        float rs = 0.f;
        #pragma unroll
        for (int w = 0; w < CHUNKS; ++w)
            rs += s_scale[g][w] * g_pr[((g0 + g) * CHUNKS + w) * DD + c];
        float S = s_S[g];
        s_in[g][128 + c] = (S > 0.f) ? rs / (S + 1e-16f) : 0.f;
    }
    __syncthreads();

    int c2 = tid & 31;            // channel-in-quarter
    int gt = (tid >> 5) & 3;      // gate index (i,f,g,o)
    int gp = tid >> 7;            // graph-quad (0..1)
    int col = gt * 128 + by * 32 + c2;

    float a0 = 0.f, a1 = 0.f, a2 = 0.f, a3 = 0.f;
    const float4* wt = (const float4*)g_Wt + col;     // + k4*512
    const float4* i0 = (const float4*)s_in[gp * 4 + 0];
    const float4* i1 = (const float4*)s_in[gp * 4 + 1];
    const float4* i2 = (const float4*)s_in[gp * 4 + 2];
    const float4* i3 = (const float4*)s_in[gp * 4 + 3];
    #pragma unroll 8
    for (int k4 = 0; k4 < 64; ++k4) {
        float4 w = wt[k4 * 512];
        float4 v0 = i0[k4], v1 = i1[k4], v2 = i2[k4], v3 = i3[k4];
        a0 += w.x * v0.x + w.y * v0.y + w.z * v0.z + w.w * v0.w;
        a1 += w.x * v1.x + w.y * v1.y + w.z * v1.z + w.w * v1.w;
        a2 += w.x * v2.x + w.y * v2.y + w.z * v2.z + w.w * v2.w;
        a3 += w.x * v3.x + w.y * v3.y + w.z * v3.z + w.w * v3.w;
    }
    float bia = g_bias[col];
    s_gate[gp * 4 + 0][c2][gt] = a0 + bia;
    s_gate[gp * 4 + 1][c2][gt] = a1 + bia;
    s_gate[gp * 4 + 2][c2][gt] = a2 + bia;
    s_gate[gp * 4 + 3][c2][gt] = a3 + bia;
    __syncthreads();

    // activation: thread -> (graph = tid>>5, channel = tid&31)
    int g = tid >> 5, ch = tid & 31;
    float gi = s_gate[g][ch][0];
    float gf = s_gate[g][ch][1];
    float gG = s_gate[g][ch][2];
    float go = s_gate[g][ch][3];
    int idx = (g0 + g) * DD + by * 32 + ch;
    float cn = sigf(gf) * g_c[idx] + sigf(gi) * tanhf(gG);
    float hn = sigf(go) * tanhf(cn);
    g_c[idx] = cn;
    g_h[idx] = hn;
}

// ---------------- final combine: r from partials, write [q, r] ---------------
__global__ __launch_bounds__(128) void combine_out_kernel(float* __restrict__ out) {
    int g = blockIdx.x, tid = threadIdx.x;
    float M = -3.4e38f;
    #pragma unroll
    for (int w = 0; w < CHUNKS; ++w) {
        float sw = g_ps[g * CHUNKS + w], mw = g_pm[g * CHUNKS + w];
        if (sw > 0.f && mw > M) M = mw;
    }
    float S = 0.f, rs = 0.f;
    #pragma unroll
    for (int w = 0; w < CHUNKS; ++w) {
        float sw = g_ps[g * CHUNKS + w];
        if (sw > 0.f) {
            float sc = __expf(g_pm[g * CHUNKS + w] - M);
            S  += sw * sc;
            rs += g_pr[(g * CHUNKS + w) * DD + tid] * sc;
        }
    }
    float rf = (S > 0.f) ? rs / (S + 1e-16f) : 0.f;
    out[g * 2 * DD + tid]      = g_h[g * DD + tid];  // q
    out[g * 2 * DD + DD + tid] = rf;                 // r
}

// ---------------- launch (8 kernels) ----------------
extern "C" void kernel_launch(void* const* d_in, const int* in_sizes, int n_in,
                              void* d_out, int out_size) {
    const float* x    = (const float*)d_in[0];
    const void*  bi   = d_in[1];
    const float* W_ih = (const float*)d_in[2];
    const float* W_hh = (const float*)d_in[3];
    const float* b_ih = (const float*)d_in[4];
    const float* b_hh = (const float*)d_in[5];
    float* out = (float*)d_out;

    setup_kernel<<<512, 256>>>(W_ih, W_hh, b_ih, b_hh, (const int*)bi);
    offsets_kernel<<<(NN / 8 + 255) / 256, 256>>>(bi);
    attn_kernel<<<NPART, 256>>>(x);
    gemm_act_kernel<<<dim3(BB / 8, 4), 256>>>();
    attn_kernel<<<NPART, 256>>>(x);
    gemm_act_kernel<<<dim3(BB / 8, 4), 256>>>();
    attn_kernel<<<NPART, 256>>>(x);
    combine_out_kernel<<<BB, 128>>>(out);
}

// round 13
// speedup vs baseline: 1.0589x; 1.0420x over previous
#include <cuda_runtime.h>
#include <cstdint>

#define NN 2000000
#define DD 128
#define BB 1024
#define STEPS 3
#define CHUNKS 8                 // chunks per graph
#define NPART (BB * CHUNKS)      // 8192 partial slots
#define TILE 16                  // nodes per pipeline stage
#define NSTAGE 4

// ---------------- device scratch (no allocs allowed) ----------------
__device__ int   g_is64;
__device__ int   g_off[BB + 1];
__device__ float g_h[BB * DD];
__device__ float g_c[BB * DD];
__device__ __align__(128) float g_Wt[64 * 512 * 4];  // [k4][gate_col][4k]
__device__ float g_bias[4 * DD];
__device__ float g_pm[NPART];              // per-chunk running max
__device__ float g_ps[NPART];              // per-chunk exp-sum
__device__ __align__(128) float g_pr[NPART * DD];    // per-chunk pooled partial (4 MB)

__device__ __forceinline__ float sigf(float v) { return 1.f / (1.f + __expf(-v)); }

__device__ __forceinline__ void cp_async16(unsigned int dst, const void* src) {
    asm volatile("cp.async.cg.shared.global [%0], [%1], 16;" :: "r"(dst), "l"(src));
}

__device__ __forceinline__ float warp_sum(float d) {
    d += __shfl_xor_sync(0xffffffffu, d, 16);
    d += __shfl_xor_sync(0xffffffffu, d, 8);
    d += __shfl_xor_sync(0xffffffffu, d, 4);
    d += __shfl_xor_sync(0xffffffffu, d, 2);
    d += __shfl_xor_sync(0xffffffffu, d, 1);
    return d;
}

// ---------------- setup: weight fold (transposed-tiled) + bias + step0 LSTM ---
// gates = [h_prev, r_prev] @ Weff^T + (b_ih + b_hh)
// Weff[gc, 0:128] = W_ih[gc, 0:128] + W_hh[gc] ; Weff[gc, 128:256] = W_ih[gc, 128:256]
// Stored transposed-tiled: g_Wt[(k>>2)*2048 + gc*4 + (k&3)] = Weff[gc][k]
// Step 0: q*=0, h=0, c=0 => gates = bias => h0,c0 closed form.
// int64 detect: sorted values < 2^31 => odd int32 words all zero.
__global__ void setup_kernel(const float* __restrict__ W_ih, const float* __restrict__ W_hh,
                             const float* __restrict__ b_ih, const float* __restrict__ b_hh,
                             const int* __restrict__ bi32) {
    int id = blockIdx.x * blockDim.x + threadIdx.x;  // 131072 threads == BB*128
    int gc = id >> 8, k = id & 255;
    float w = W_ih[gc * 256 + k];
    if (k < 128) w += W_hh[gc * 128 + k];
    g_Wt[(k >> 2) * 2048 + gc * 4 + (k & 3)] = w;
    if (id < 4 * DD) g_bias[id] = b_ih[id] + b_hh[id];

    // step-0 LSTM state (one thread per (graph, channel))
    int c = id & 127;
    float gi = b_ih[c]       + b_hh[c];
    float gG = b_ih[c + 256] + b_hh[c + 256];
    float go = b_ih[c + 384] + b_hh[c + 384];
    float cn = sigf(gi) * tanhf(gG);        // sig(f)*c0 term is 0
    float hn = sigf(go) * tanhf(cn);
    g_c[id] = cn;
    g_h[id] = hn;

    if (id == 0)
        g_is64 = (bi32[NN - 1] == 0 && bi32[(NN / 2) | 1] == 0 &&
                  bi32[(NN / 4) | 1] == 0) ? 1 : 0;
}

__device__ __forceinline__ int load_bi(const void* bi, int i, int is64) {
    if (is64) return (int)((const long long*)bi)[i];
    return ((const int*)bi)[i];
}

// ---------------- graph start offsets (batch_index sorted), 8 elems/thread ----
__global__ void offsets_kernel(const void* __restrict__ bi) {
    int t = blockIdx.x * blockDim.x + threadIdx.x;
    if (t >= NN / 8) return;
    int i0 = t * 8;
    int is64 = g_is64;
    int v[8];
    if (is64) {
        const longlong2* p = (const longlong2*)bi + t * 4;
        longlong2 a = p[0], b = p[1], c = p[2], d = p[3];
        v[0] = (int)a.x; v[1] = (int)a.y; v[2] = (int)b.x; v[3] = (int)b.y;
        v[4] = (int)c.x; v[5] = (int)c.y; v[6] = (int)d.x; v[7] = (int)d.y;
    } else {
        const int4* p = (const int4*)bi + t * 2;
        int4 a = p[0], b = p[1];
        v[0] = a.x; v[1] = a.y; v[2] = a.z; v[3] = a.w;
        v[4] = b.x; v[5] = b.y; v[6] = b.z; v[7] = b.w;
    }
    int prev = (i0 == 0) ? -1 : load_bi(bi, i0 - 1, is64);
    #pragma unroll
    for (int j = 0; j < 8; ++j) {
        for (int g = prev + 1; g <= v[j]; ++g) g_off[g] = i0 + j;
        prev = v[j];
    }
    if (i0 + 8 == NN)
        for (int g = prev + 1; g <= BB; ++g) g_off[g] = NN;
}

// ---------------- chunked online-softmax attention pooling (partials) --------
// Block b handles chunk (b & 7) of graph (b >> 3). 4-stage cp.async pipeline,
// 3 tiles in flight; 6 blocks/SM.
__global__ __launch_bounds__(256, 6) void attn_kernel(const float* __restrict__ x) {
    __shared__ float4 s_tile[NSTAGE][TILE * 32];   // 4 x 8KB
    __shared__ float  s_q[128];
    __shared__ float  s_r[8][128];
    __shared__ float  s_m[8];
    __shared__ float  s_s[8];

    int b = blockIdx.x;
    int g = b >> 3, cidx = b & 7;
    int tid = threadIdx.x;
    int lane = tid & 31, wid = tid >> 5;

    if (tid < 128) s_q[tid] = g_h[g * DD + tid];

    int gs = g_off[g], ge = g_off[g + 1], len = ge - gs;
    int start = gs + (len * cidx) / CHUNKS;
    int end   = gs + (len * (cidx + 1)) / CHUNKS;
    int nt = (end > start) ? (end - start + TILE - 1) / TILE : 0;

    unsigned int s_base = (unsigned int)__cvta_generic_to_shared(s_tile);
    const float4* x4 = (const float4*)x;

    // issue tile t into buffer t % NSTAGE (clamped tail); always commit a group
    auto issue_tile = [&](int t) {
        if (t < nt) {
            int base = start + t * TILE;
            unsigned int dst0 = s_base + (unsigned int)((t % NSTAGE) * (TILE * 32) << 4);
            #pragma unroll
            for (int k = 0; k < 2; ++k) {
                int c = tid + 256 * k;            // 0..511 (16B chunk index)
                int node = base + (c >> 5);
                if (node >= end) node = end - 1;  // tail clamp: L2-hit duplicate
                cp_async16(dst0 + ((unsigned int)c << 4),
                           x4 + (size_t)node * 32 + (c & 31));
            }
        }
        asm volatile("cp.async.commit_group;" ::: "memory");
    };

    issue_tile(0);
    issue_tile(1);
    issue_tile(2);

    float m = -3.4e38f;
    float s = 0.f;
    float4 racc = make_float4(0.f, 0.f, 0.f, 0.f);
    float4 q4;

    __syncthreads();              // s_q visible (also covers nt==0 path)
    q4 = ((const float4*)s_q)[lane];

    for (int t = 0; t < nt; ++t) {
        asm volatile("cp.async.wait_group 2;" ::: "memory");  // tile t ready
        __syncthreads();          // all warps done with buf (t-1)%4 == (t+3)%4
        issue_tile(t + 3);        // refill newest stage

        const float4* tile = s_tile[t % NSTAGE];
        int nbase = start + t * TILE;
        float4 xv[2];
        float e[2];
        #pragma unroll
        for (int j = 0; j < 2; ++j) {
            int nl = wid * 2 + j;                 // 0..15
            xv[j] = tile[(nl << 5) + lane];
            float d = xv[j].x * q4.x + xv[j].y * q4.y +
                      xv[j].z * q4.z + xv[j].w * q4.w;
            d = warp_sum(d);
            e[j] = (nbase + nl < end) ? d : -3.4e38f;  // padded -> p = 0
        }
        float em = fmaxf(e[0], e[1]);
        if (em > m) {             // rare, warp-uniform
            float sc = __expf(m - em);
            s *= sc;
            racc.x *= sc; racc.y *= sc; racc.z *= sc; racc.w *= sc;
            m = em;
        }
        #pragma unroll
        for (int j = 0; j < 2; ++j) {
            float p = __expf(e[j] - m);
            s += p;
            racc.x += p * xv[j].x; racc.y += p * xv[j].y;
            racc.z += p * xv[j].z; racc.w += p * xv[j].w;
        }
    }

    if (lane == 0) { s_m[wid] = m; s_s[wid] = s; }
    ((float4*)s_r[wid])[lane] = racc;
    __syncthreads();

    // combine 8 per-warp partials -> per-chunk partial
    if (tid < 128) {
        float M = -3.4e38f;
        #pragma unroll
        for (int w = 0; w < 8; ++w)
            if (s_s[w] > 0.f && s_m[w] > M) M = s_m[w];
        float S = 0.f, rs = 0.f;
        #pragma unroll
        for (int w = 0; w < 8; ++w) {
            if (s_s[w] > 0.f) {
                float sc = __expf(s_m[w] - M);
                S  += s_s[w] * sc;
                rs += s_r[w][tid] * sc;
            }
        }
        g_pr[b * DD + tid] = rs;
        if (tid == 0) { g_pm[b] = M; g_ps[b] = S; }
    }
}

// ---------------- fused: combine partials -> r, GEMM (cp.async weights), act -
// Grid (128, 4): bx = graph octet, by = channel quarter (32 channels x 4 gates).
// Weights staged in smem via double-buffered cp.async (8 k4-steps = 16KB/stage)
// so the FFMA stream never waits on L2 latency.
#define K4C 8                    // k4 steps per weight stage
__global__ __launch_bounds__(256) void gemm_act_kernel() {
    __shared__ float  s_in[8][256];        // [h | r] for 8 graphs (8 KB)
    __shared__ float  s_gate[8][32][4];    // [graph][channel][gate] (4 KB)
    __shared__ float  s_scale[8][CHUNKS];
    __shared__ float  s_S[8];
    __shared__ float4 s_w[2][K4C * 128];   // 2 x 16 KB weight stages

    int g0 = blockIdx.x * 8;
    int by = blockIdx.y;
    int tid = threadIdx.x;

    unsigned int swb = (unsigned int)__cvta_generic_to_shared(s_w);

    // stage st covers k4 range [kb, kb+8); each thread moves 4 x 16B.
    // src col for chunk idx: kk = idx>>7, cc = idx&127 -> gate gt=cc>>5, chan c2=cc&31
    auto issue_w = [&](int st, int kb) {
        if (kb < 64) {
            #pragma unroll
            for (int q = 0; q < 4; ++q) {
                int idx = tid + q * 256;          // 0..1023
                int kk = idx >> 7;
                int cc = idx & 127;
                int gt = cc >> 5, c2 = cc & 31;
                const float* src = g_Wt + (kb + kk) * 2048 + (gt * 128 + by * 32 + c2) * 4;
                cp_async16(swb + (unsigned int)((st * (K4C * 128) + idx) << 4), src);
            }
        }
        asm volatile("cp.async.commit_group;" ::: "memory");
    };

    issue_w(0, 0);   // first weight stage in flight during prologue

    // per-graph softmax-combine scales (8 threads)
    if (tid < 8) {
        int g = g0 + tid;
        float M = -3.4e38f;
        #pragma unroll
        for (int w = 0; w < CHUNKS; ++w) {
            float sw = g_ps[g * CHUNKS + w], mw = g_pm[g * CHUNKS + w];
            if (sw > 0.f && mw > M) M = mw;
        }
        float S = 0.f;
        #pragma unroll
        for (int w = 0; w < CHUNKS; ++w) {
            float sw = g_ps[g * CHUNKS + w];
            float sc = (sw > 0.f) ? __expf(g_pm[g * CHUNKS + w] - M) : 0.f;
            s_scale[tid][w] = sc;
            S += sw * sc;
        }
        s_S[tid] = S;
    }
    // h into s_in[:, 0:128]
    for (int it = tid; it < 8 * 128; it += 256) {
        int g = it >> 7, c = it & 127;
        s_in[g][c] = g_h[(g0 + g) * DD + c];
    }
    __syncthreads();
    // r into s_in[:, 128:256] (combine partials; g_pr reads are L2 hits)
    for (int it = tid; it < 8 * 128; it += 256) {
        int g = it >> 7, c = it & 127;
        float rs = 0.f;
        #pragma unroll
        for (int w = 0; w < CHUNKS; ++w)
            rs += s_scale[g][w] * g_pr[((g0 + g) * CHUNKS + w) * DD + c];
        float S = s_S[g];
        s_in[g][128 + c] = (S > 0.f) ? rs / (S + 1e-16f) : 0.f;
    }
    __syncthreads();

    int c2 = tid & 31;            // channel-in-quarter
    int gt = (tid >> 5) & 3;      // gate index (i,f,g,o)
    int gp = tid >> 7;            // graph-quad (0..1)
    int wcol = gt * 32 + c2;      // column index within the staged 128

    float a0 = 0.f, a1 = 0.f, a2 = 0.f, a3 = 0.f;
    const float4* i0 = (const float4*)s_in[gp * 4 + 0];
    const float4* i1 = (const float4*)s_in[gp * 4 + 1];
    const float4* i2 = (const float4*)s_in[gp * 4 + 2];
    const float4* i3 = (const float4*)s_in[gp * 4 + 3];

    for (int t = 0; t < 64 / K4C; ++t) {
        asm volatile("cp.async.wait_group 0;" ::: "memory");  // stage t ready
        __syncthreads();          // all warps past compute(t-1) before refill
        issue_w((t + 1) & 1, (t + 1) * K4C);   // in flight during compute(t)

        const float4* ws = s_w[t & 1];
        #pragma unroll
        for (int kk = 0; kk < K4C; ++kk) {
            float4 w = ws[kk * 128 + wcol];
            int k4 = t * K4C + kk;
            float4 v0 = i0[k4], v1 = i1[k4], v2 = i2[k4], v3 = i3[k4];
            a0 += w.x * v0.x + w.y * v0.y + w.z * v0.z + w.w * v0.w;
            a1 += w.x * v1.x + w.y * v1.y + w.z * v1.z + w.w * v1.w;
            a2 += w.x * v2.x + w.y * v2.y + w.z * v2.z + w.w * v2.w;
            a3 += w.x * v3.x + w.y * v3.y + w.z * v3.z + w.w * v3.w;
        }
        __syncthreads();          // done with buffer t&1 before next refill
    }

    int col = gt * 128 + by * 32 + c2;
    float bia = g_bias[col];
    s_gate[gp * 4 + 0][c2][gt] = a0 + bia;
    s_gate[gp * 4 + 1][c2][gt] = a1 + bia;
    s_gate[gp * 4 + 2][c2][gt] = a2 + bia;
    s_gate[gp * 4 + 3][c2][gt] = a3 + bia;
    __syncthreads();

    // activation: thread -> (graph = tid>>5, channel = tid&31)
    int g = tid >> 5, ch = tid & 31;
    float gi = s_gate[g][ch][0];
    float gf = s_gate[g][ch][1];
    float gG = s_gate[g][ch][2];
    float go = s_gate[g][ch][3];
    int idx = (g0 + g) * DD + by * 32 + ch;
    float cn = sigf(gf) * g_c[idx] + sigf(gi) * tanhf(gG);
    float hn = sigf(go) * tanhf(cn);
    g_c[idx] = cn;
    g_h[idx] = hn;
}

// ---------------- final combine: r from partials, write [q, r] ---------------
__global__ __launch_bounds__(128) void combine_out_kernel(float* __restrict__ out) {
    int g = blockIdx.x, tid = threadIdx.x;
    float M = -3.4e38f;
    #pragma unroll
    for (int w = 0; w < CHUNKS; ++w) {
        float sw = g_ps[g * CHUNKS + w], mw = g_pm[g * CHUNKS + w];
        if (sw > 0.f && mw > M) M = mw;
    }
    float S = 0.f, rs = 0.f;
    #pragma unroll
    for (int w = 0; w < CHUNKS; ++w) {
        float sw = g_ps[g * CHUNKS + w];
        if (sw > 0.f) {
            float sc = __expf(g_pm[g * CHUNKS + w] - M);
            S  += sw * sc;
            rs += g_pr[(g * CHUNKS + w) * DD + tid] * sc;
        }
    }
    float rf = (S > 0.f) ? rs / (S + 1e-16f) : 0.f;
    out[g * 2 * DD + tid]      = g_h[g * DD + tid];  // q
    out[g * 2 * DD + DD + tid] = rf;                 // r
}

// ---------------- launch (8 kernels) ----------------
extern "C" void kernel_launch(void* const* d_in, const int* in_sizes, int n_in,
                              void* d_out, int out_size) {
    const float* x    = (const float*)d_in[0];
    const void*  bi   = d_in[1];
    const float* W_ih = (const float*)d_in[2];
    const float* W_hh = (const float*)d_in[3];
    const float* b_ih = (const float*)d_in[4];
    const float* b_hh = (const float*)d_in[5];
    float* out = (float*)d_out;

    setup_kernel<<<512, 256>>>(W_ih, W_hh, b_ih, b_hh, (const int*)bi);
    offsets_kernel<<<(NN / 8 + 255) / 256, 256>>>(bi);
    attn_kernel<<<NPART, 256>>>(x);
    gemm_act_kernel<<<dim3(BB / 8, 4), 256>>>();
    attn_kernel<<<NPART, 256>>>(x);
    gemm_act_kernel<<<dim3(BB / 8, 4), 256>>>();
    attn_kernel<<<NPART, 256>>>(x);
    combine_out_kernel<<<BB, 128>>>(out);
}

// round 14
// speedup vs baseline: 1.0621x; 1.0030x over previous
#include <cuda_runtime.h>
#include <cstdint>

#define NN 2000000
#define DD 128
#define BB 1024
#define STEPS 3
#define CHUNKS 8                 // chunks per graph
#define NPART (BB * CHUNKS)      // 8192 partial slots
#define TILE 16                  // nodes per pipeline stage
#define NSTAGE 4

// ---------------- device scratch (no allocs allowed) ----------------
__device__ int   g_is64;
__device__ int   g_off[BB + 1];
__device__ float g_h[BB * DD];
__device__ float g_c[BB * DD];
__device__ __align__(128) float g_Wt[64 * 512 * 4];  // [k4][gate_col][4k]
__device__ float g_bias[4 * DD];
__device__ float g_pm[NPART];              // per-chunk running max
__device__ float g_ps[NPART];              // per-chunk exp-sum
__device__ __align__(128) float g_pr[NPART * DD];    // per-chunk pooled partial (4 MB)

__device__ __forceinline__ float sigf(float v) { return 1.f / (1.f + __expf(-v)); }

__device__ __forceinline__ void cp_async16(unsigned int dst, const void* src) {
    asm volatile("cp.async.cg.shared.global [%0], [%1], 16;" :: "r"(dst), "l"(src));
}

__device__ __forceinline__ float warp_sum(float d) {
    d += __shfl_xor_sync(0xffffffffu, d, 16);
    d += __shfl_xor_sync(0xffffffffu, d, 8);
    d += __shfl_xor_sync(0xffffffffu, d, 4);
    d += __shfl_xor_sync(0xffffffffu, d, 2);
    d += __shfl_xor_sync(0xffffffffu, d, 1);
    return d;
}

// ---------------- setup: weight fold (transposed-tiled) + bias + step0 LSTM ---
__global__ void setup_kernel(const float* __restrict__ W_ih, const float* __restrict__ W_hh,
                             const float* __restrict__ b_ih, const float* __restrict__ b_hh,
                             const int* __restrict__ bi32) {
    int id = blockIdx.x * blockDim.x + threadIdx.x;  // 131072 threads == BB*128
    int gc = id >> 8, k = id & 255;
    float w = W_ih[gc * 256 + k];
    if (k < 128) w += W_hh[gc * 128 + k];
    g_Wt[(k >> 2) * 2048 + gc * 4 + (k & 3)] = w;
    if (id < 4 * DD) g_bias[id] = b_ih[id] + b_hh[id];

    // step-0 LSTM state (q*=0, h=0, c=0 => gates = bias)
    int c = id & 127;
    float gi = b_ih[c]       + b_hh[c];
    float gG = b_ih[c + 256] + b_hh[c + 256];
    float go = b_ih[c + 384] + b_hh[c + 384];
    float cn = sigf(gi) * tanhf(gG);
    float hn = sigf(go) * tanhf(cn);
    g_c[id] = cn;
    g_h[id] = hn;

    if (id == 0)
        g_is64 = (bi32[NN - 1] == 0 && bi32[(NN / 2) | 1] == 0 &&
                  bi32[(NN / 4) | 1] == 0) ? 1 : 0;
}

__device__ __forceinline__ int load_bi(const void* bi, int i, int is64) {
    if (is64) return (int)((const long long*)bi)[i];
    return ((const int*)bi)[i];
}

// ---------------- graph start offsets (batch_index sorted), 8 elems/thread ----
__global__ void offsets_kernel(const void* __restrict__ bi) {
    int t = blockIdx.x * blockDim.x + threadIdx.x;
    if (t >= NN / 8) return;
    int i0 = t * 8;
    int is64 = g_is64;
    int v[8];
    if (is64) {
        const longlong2* p = (const longlong2*)bi + t * 4;
        longlong2 a = p[0], b = p[1], c = p[2], d = p[3];
        v[0] = (int)a.x; v[1] = (int)a.y; v[2] = (int)b.x; v[3] = (int)b.y;
        v[4] = (int)c.x; v[5] = (int)c.y; v[6] = (int)d.x; v[7] = (int)d.y;
    } else {
        const int4* p = (const int4*)bi + t * 2;
        int4 a = p[0], b = p[1];
        v[0] = a.x; v[1] = a.y; v[2] = a.z; v[3] = a.w;
        v[4] = b.x; v[5] = b.y; v[6] = b.z; v[7] = b.w;
    }
    int prev = (i0 == 0) ? -1 : load_bi(bi, i0 - 1, is64);
    #pragma unroll
    for (int j = 0; j < 8; ++j) {
        for (int g = prev + 1; g <= v[j]; ++g) g_off[g] = i0 + j;
        prev = v[j];
    }
    if (i0 + 8 == NN)
        for (int g = prev + 1; g <= BB; ++g) g_off[g] = NN;
}

// ---------------- chunked online-softmax attention pooling (partials) --------
// PDL: g_off and x are stale data (written >=2 kernels back) -> read/prefetch
// BEFORE cudaGridDependencySynchronize(); g_h (fresh from gemm_act) after.
__global__ __launch_bounds__(256, 6) void attn_kernel(const float* __restrict__ x) {
    __shared__ float4 s_tile[NSTAGE][TILE * 32];   // 4 x 8KB
    __shared__ float  s_q[128];
    __shared__ float  s_r[8][128];
    __shared__ float  s_m[8];
    __shared__ float  s_s[8];

    int b = blockIdx.x;
    int g = b >> 3, cidx = b & 7;
    int tid = threadIdx.x;
    int lane = tid & 31, wid = tid >> 5;

    int gs = g_off[g], ge = g_off[g + 1], len = ge - gs;
    int start = gs + (len * cidx) / CHUNKS;
    int end   = gs + (len * (cidx + 1)) / CHUNKS;
    int nt = (end > start) ? (end - start + TILE - 1) / TILE : 0;

    unsigned int s_base = (unsigned int)__cvta_generic_to_shared(s_tile);
    const float4* x4 = (const float4*)x;

    // issue tile t into buffer t % NSTAGE (clamped tail); always commit a group
    auto issue_tile = [&](int t) {
        if (t < nt) {
            int base = start + t * TILE;
            unsigned int dst0 = s_base + (unsigned int)((t % NSTAGE) * (TILE * 32) << 4);
            #pragma unroll
            for (int k = 0; k < 2; ++k) {
                int c = tid + 256 * k;            // 0..511 (16B chunk index)
                int node = base + (c >> 5);
                if (node >= end) node = end - 1;  // tail clamp: L2-hit duplicate
                cp_async16(dst0 + ((unsigned int)c << 4),
                           x4 + (size_t)node * 32 + (c & 31));
            }
        }
        asm volatile("cp.async.commit_group;" ::: "memory");
    };

    issue_tile(0);
    issue_tile(1);
    issue_tile(2);

    cudaGridDependencySynchronize();   // gate fresh g_h (no-op for non-PDL)

    if (tid < 128) s_q[tid] = g_h[g * DD + tid];

    float m = -3.4e38f;
    float s = 0.f;
    float4 racc = make_float4(0.f, 0.f, 0.f, 0.f);
    float4 q4;

    __syncthreads();              // s_q visible (also covers nt==0 path)
    q4 = ((const float4*)s_q)[lane];

    for (int t = 0; t < nt; ++t) {
        asm volatile("cp.async.wait_group 2;" ::: "memory");  // tile t ready
        __syncthreads();          // all warps done with buf (t-1)%4 == (t+3)%4
        issue_tile(t + 3);        // refill newest stage

        const float4* tile = s_tile[t % NSTAGE];
        int nbase = start + t * TILE;
        float4 xv[2];
        float e[2];
        #pragma unroll
        for (int j = 0; j < 2; ++j) {
            int nl = wid * 2 + j;                 // 0..15
            xv[j] = tile[(nl << 5) + lane];
            float d = xv[j].x * q4.x + xv[j].y * q4.y +
                      xv[j].z * q4.z + xv[j].w * q4.w;
            d = warp_sum(d);
            e[j] = (nbase + nl < end) ? d : -3.4e38f;  // padded -> p = 0
        }
        float em = fmaxf(e[0], e[1]);
        if (em > m) {             // rare, warp-uniform
            float sc = __expf(m - em);
            s *= sc;
            racc.x *= sc; racc.y *= sc; racc.z *= sc; racc.w *= sc;
            m = em;
        }
        #pragma unroll
        for (int j = 0; j < 2; ++j) {
            float p = __expf(e[j] - m);
            s += p;
            racc.x += p * xv[j].x; racc.y += p * xv[j].y;
            racc.z += p * xv[j].z; racc.w += p * xv[j].w;
        }
    }

    if (lane == 0) { s_m[wid] = m; s_s[wid] = s; }
    ((float4*)s_r[wid])[lane] = racc;
    __syncthreads();

    // combine 8 per-warp partials -> per-chunk partial
    if (tid < 128) {
        float M = -3.4e38f;
        #pragma unroll
        for (int w = 0; w < 8; ++w)
            if (s_s[w] > 0.f && s_m[w] > M) M = s_m[w];
        float S = 0.f, rs = 0.f;
        #pragma unroll
        for (int w = 0; w < 8; ++w) {
            if (s_s[w] > 0.f) {
                float sc = __expf(s_m[w] - M);
                S  += s_s[w] * sc;
                rs += s_r[w][tid] * sc;
            }
        }
        g_pr[b * DD + tid] = rs;
        if (tid == 0) { g_pm[b] = M; g_ps[b] = S; }
    }
}

// ---------------- fused: combine partials -> r, GEMM (cp.async weights), act -
// PDL: weight stage 0 (g_Wt, stale) prefetched before the grid-dep sync.
#define K4C 8                    // k4 steps per weight stage
__global__ __launch_bounds__(256) void gemm_act_kernel() {
    __shared__ float  s_in[8][256];        // [h | r] for 8 graphs (8 KB)
    __shared__ float  s_gate[8][32][4];    // [graph][channel][gate] (4 KB)
    __shared__ float  s_scale[8][CHUNKS];
    __shared__ float  s_S[8];
    __shared__ float4 s_w[2][K4C * 128];   // 2 x 16 KB weight stages

    int g0 = blockIdx.x * 8;
    int by = blockIdx.y;
    int tid = threadIdx.x;

    unsigned int swb = (unsigned int)__cvta_generic_to_shared(s_w);

    auto issue_w = [&](int st, int kb) {
        if (kb < 64) {
            #pragma unroll
            for (int q = 0; q < 4; ++q) {
                int idx = tid + q * 256;          // 0..1023
                int kk = idx >> 7;
                int cc = idx & 127;
                int gt = cc >> 5, c2 = cc & 31;
                const float* src = g_Wt + (kb + kk) * 2048 + (gt * 128 + by * 32 + c2) * 4;
                cp_async16(swb + (unsigned int)((st * (K4C * 128) + idx) << 4), src);
            }
        }
        asm volatile("cp.async.commit_group;" ::: "memory");
    };

    issue_w(0, 0);   // stale weights in flight during predecessor tail

    cudaGridDependencySynchronize();   // gate fresh g_pm/g_ps/g_pr/g_h

    // per-graph softmax-combine scales (8 threads)
    if (tid < 8) {
        int g = g0 + tid;
        float M = -3.4e38f;
        #pragma unroll
        for (int w = 0; w < CHUNKS; ++w) {
            float sw = g_ps[g * CHUNKS + w], mw = g_pm[g * CHUNKS + w];
            if (sw > 0.f && mw > M) M = mw;
        }
        float S = 0.f;
        #pragma unroll
        for (int w = 0; w < CHUNKS; ++w) {
            float sw = g_ps[g * CHUNKS + w];
            float sc = (sw > 0.f) ? __expf(g_pm[g * CHUNKS + w] - M) : 0.f;
            s_scale[tid][w] = sc;
            S += sw * sc;
        }
        s_S[tid] = S;
    }
    // h into s_in[:, 0:128]
    for (int it = tid; it < 8 * 128; it += 256) {
        int g = it >> 7, c = it & 127;
        s_in[g][c] = g_h[(g0 + g) * DD + c];
    }
    __syncthreads();
    // r into s_in[:, 128:256] (combine partials; g_pr reads are L2 hits)
    for (int it = tid; it < 8 * 128; it += 256) {
        int g = it >> 7, c = it & 127;
        float rs = 0.f;
        #pragma unroll
        for (int w = 0; w < CHUNKS; ++w)
            rs += s_scale[g][w] * g_pr[((g0 + g) * CHUNKS + w) * DD + c];
        float S = s_S[g];
        s_in[g][128 + c] = (S > 0.f) ? rs / (S + 1e-16f) : 0.f;
    }
    __syncthreads();

    int c2 = tid & 31;            // channel-in-quarter
    int gt = (tid >> 5) & 3;      // gate index (i,f,g,o)
    int gp = tid >> 7;            // graph-quad (0..1)
    int wcol = gt * 32 + c2;      // column index within the staged 128

    float a0 = 0.f, a1 = 0.f, a2 = 0.f, a3 = 0.f;
    const float4* i0 = (const float4*)s_in[gp * 4 + 0];
    const float4* i1 = (const float4*)s_in[gp * 4 + 1];
    const float4* i2 = (const float4*)s_in[gp * 4 + 2];
    const float4* i3 = (const float4*)s_in[gp * 4 + 3];

    for (int t = 0; t < 64 / K4C; ++t) {
        asm volatile("cp.async.wait_group 0;" ::: "memory");  // stage t ready
        __syncthreads();          // all warps past compute(t-1) before refill
        issue_w((t + 1) & 1, (t + 1) * K4C);   // in flight during compute(t)

        const float4* ws = s_w[t & 1];
        #pragma unroll
        for (int kk = 0; kk < K4C; ++kk) {
            float4 w = ws[kk * 128 + wcol];
            int k4 = t * K4C + kk;
            float4 v0 = i0[k4], v1 = i1[k4], v2 = i2[k4], v3 = i3[k4];
            a0 += w.x * v0.x + w.y * v0.y + w.z * v0.z + w.w * v0.w;
            a1 += w.x * v1.x + w.y * v1.y + w.z * v1.z + w.w * v1.w;
            a2 += w.x * v2.x + w.y * v2.y + w.z * v2.z + w.w * v2.w;
            a3 += w.x * v3.x + w.y * v3.y + w.z * v3.z + w.w * v3.w;
        }
        __syncthreads();          // done with buffer t&1 before next refill
    }

    int col = gt * 128 + by * 32 + c2;
    float bia = g_bias[col];
    s_gate[gp * 4 + 0][c2][gt] = a0 + bia;
    s_gate[gp * 4 + 1][c2][gt] = a1 + bia;
    s_gate[gp * 4 + 2][c2][gt] = a2 + bia;
    s_gate[gp * 4 + 3][c2][gt] = a3 + bia;
    __syncthreads();

    // activation: thread -> (graph = tid>>5, channel = tid&31)
    int g = tid >> 5, ch = tid & 31;
    float gi = s_gate[g][ch][0];
    float gf = s_gate[g][ch][1];
    float gG = s_gate[g][ch][2];
    float go = s_gate[g][ch][3];
    int idx = (g0 + g) * DD + by * 32 + ch;
    float cn = sigf(gf) * g_c[idx] + sigf(gi) * tanhf(gG);
    float hn = sigf(go) * tanhf(cn);
    g_c[idx] = cn;
    g_h[idx] = hn;
}

// ---------------- final combine: r from partials, write [q, r] ---------------
__global__ __launch_bounds__(128) void combine_out_kernel(float* __restrict__ out) {
    cudaGridDependencySynchronize();
    int g = blockIdx.x, tid = threadIdx.x;
    float M = -3.4e38f;
    #pragma unroll
    for (int w = 0; w < CHUNKS; ++w) {
        float sw = g_ps[g * CHUNKS + w], mw = g_pm[g * CHUNKS + w];
        if (sw > 0.f && mw > M) M = mw;
    }
    float S = 0.f, rs = 0.f;
    #pragma unroll
    for (int w = 0; w < CHUNKS; ++w) {
        float sw = g_ps[g * CHUNKS + w];
        if (sw > 0.f) {
            float sc = __expf(g_pm[g * CHUNKS + w] - M);
            S  += sw * sc;
            rs += g_pr[(g * CHUNKS + w) * DD + tid] * sc;
        }
    }
    float rf = (S > 0.f) ? rs / (S + 1e-16f) : 0.f;
    out[g * 2 * DD + tid]      = g_h[g * DD + tid];  // q
    out[g * 2 * DD + DD + tid] = rf;                 // r
}

// ---------------- launch (8 kernels; PDL on the step chain) ----------------
template <typename... Args>
static void launch_pdl(void (*kern)(Args...), dim3 grid, dim3 block, Args... args) {
    cudaLaunchConfig_t cfg = {};
    cfg.gridDim = grid;
    cfg.blockDim = block;
    cfg.dynamicSmemBytes = 0;
    cfg.stream = 0;
    cudaLaunchAttribute at[1];
    at[0].id = cudaLaunchAttributeProgrammaticStreamSerialization;
    at[0].val.programmaticStreamSerializationAllowed = 1;
    cfg.attrs = at;
    cfg.numAttrs = 1;
    cudaLaunchKernelEx(&cfg, kern, args...);
}

extern "C" void kernel_launch(void* const* d_in, const int* in_sizes, int n_in,
                              void* d_out, int out_size) {
    const float* x    = (const float*)d_in[0];
    const void*  bi   = d_in[1];
    const float* W_ih = (const float*)d_in[2];
    const float* W_hh = (const float*)d_in[3];
    const float* b_ih = (const float*)d_in[4];
    const float* b_hh = (const float*)d_in[5];
    float* out = (float*)d_out;

    setup_kernel<<<512, 256>>>(W_ih, W_hh, b_ih, b_hh, (const int*)bi);
    offsets_kernel<<<(NN / 8 + 255) / 256, 256>>>(bi);
    attn_kernel<<<NPART, 256>>>(x);            // no PDL: reads g_off pre-sync
    launch_pdl(gemm_act_kernel, dim3(BB / 8, 4), dim3(256));
    launch_pdl(attn_kernel, dim3(NPART), dim3(256), x);
    launch_pdl(gemm_act_kernel, dim3(BB / 8, 4), dim3(256));
    launch_pdl(attn_kernel, dim3(NPART), dim3(256), x);
    launch_pdl(combine_out_kernel, dim3(BB), dim3(128), out);
}